// round 16
// baseline (speedup 1.0000x reference)
#include <cuda_runtime.h>
#include <cstdint>
#include <math.h>

#define EPSV 1e-4f
#define NM   3249            // 57*57 floats per matrix
#define WPB  8               // warps (=matrices) per block
#define BLOCKS 1024          // 8192 matrices / 8
#define BLK_PER_B 8          // 64 matrices per batch / 8 per block

// Scratch (allocation-free). Counter reset by last arriver -> graph-replay safe.
__device__ float g_a[128 * 64 * 3];
__device__ int   g_cnt[128];

__global__ void __launch_bounds__(256)
fused_kernel(const float* __restrict__ x,
             const float* __restrict__ W1,
             const float* __restrict__ W2,
             const float* __restrict__ W3,
             const float* __restrict__ lin_w,
             const float* __restrict__ lin_b,
             const float* __restrict__ alpha,
             float* __restrict__ out) {
    __shared__ float2 sm_pq[57];
    __shared__ float  sm_w23[40];
    __shared__ float  sm_scan[260];     // a0|a1|a2 (64 each) + lw(51) + lb(17)
    __shared__ int    sm_last;

    const int tid  = threadIdx.x;
    const int wid  = tid >> 5;
    const int lane = tid & 31;
    const int blk  = blockIdx.x;

    // --- P = W1@W2@W3 into sm_pq ---
    if (tid < 40) {
        int j = tid >> 1, u = tid & 1;
        float s = 0.f;
        #pragma unroll
        for (int k = 0; k < 10; k++) s = fmaf(__ldg(W2 + j * 10 + k), __ldg(W3 + k * 2 + u), s);
        sm_w23[tid] = s;
    }
    __syncthreads();
    if (tid < 114) {
        int i = tid >> 1, u = tid & 1;
        float s = 0.f;
        #pragma unroll
        for (int j = 0; j < 20; j++) s = fmaf(__ldg(W1 + i * 20 + j), sm_w23[j * 2 + u], s);
        ((float*)&sm_pq[i])[u] = s;
    }
    __syncthreads();

    // --- Per-warp matrix: c = P^T X P, register-resident column weights ---
    const int gm = blk * WPB + wid;              // matrix id 0..8191
    const float* xm = x + (size_t)gm * NM;

    const float2 pk0 = sm_pq[lane];              // weight for k = lane
    const bool   hi  = (lane < 25);
    const float2 pk1 = hi ? sm_pq[32 + lane] : make_float2(0.f, 0.f);
    const int    off1 = hi ? (32 + lane) : 0;    // safe address (value masked by pk1=0)

    float c00 = 0.f, c01 = 0.f, c11 = 0.f;

    // 8-row batches: issue 16 independent loads, then the FMA block.
    #pragma unroll 1
    for (int base = 0; base < 56; base += 8) {
        float a0[8], a1[8];
        #pragma unroll
        for (int r = 0; r < 8; r++) {
            const float* rp = xm + 57 * (base + r);
            a0[r] = __ldg(rp + lane);
            a1[r] = __ldg(rp + off1);
        }
        #pragma unroll
        for (int r = 0; r < 8; r++) {
            float2 pi = sm_pq[base + r];
            float u = fmaf(a1[r], pk1.x, a0[r] * pk0.x);
            float v = fmaf(a1[r], pk1.y, a0[r] * pk0.y);
            c00 = fmaf(pi.x, u, c00);
            c01 = fmaf(pi.x, v, c01);
            c11 = fmaf(pi.y, v, c11);
        }
    }
    {   // row 56
        const float* rp = xm + 57 * 56;
        float a0 = __ldg(rp + lane);
        float a1 = __ldg(rp + off1);
        float2 pi = sm_pq[56];
        float u = fmaf(a1, pk1.x, a0 * pk0.x);
        float v = fmaf(a1, pk1.y, a0 * pk0.y);
        c00 = fmaf(pi.x, u, c00);
        c01 = fmaf(pi.x, v, c01);
        c11 = fmaf(pi.y, v, c11);
    }

    // warp reduction
    #pragma unroll
    for (int o = 16; o; o >>= 1) {
        c00 += __shfl_xor_sync(0xFFFFFFFFu, c00, o);
        c01 += __shfl_xor_sync(0xFFFFFFFFu, c01, o);
        c11 += __shfl_xor_sync(0xFFFFFFFFu, c11, o);
    }
    if (lane == 0) {
        float* o = g_a + (size_t)gm * 3;
        o[0] = c00; o[1] = c01; o[2] = c11;
    }
    __threadfence();
    __syncthreads();

    const int b = blk >> 3;                      // 8 blocks per batch
    if (tid == 0) {
        int old = atomicAdd(&g_cnt[b], 1);
        sm_last = (old == BLK_PER_B - 1);
        if (old == BLK_PER_B - 1) g_cnt[b] = 0;  // reset for graph replay
    }
    __syncthreads();
    if (!sm_last) return;

    // --- Scan phase (only last-arriving block per b) ---
    __threadfence();                             // acquire
    float* a0s = sm_scan;
    float* a1s = sm_scan + 64;
    float* a2s = sm_scan + 128;
    float* lw  = sm_scan + 192;                  // 51
    float* lb  = sm_scan + 243;                  // 17
    if (tid < 64) {
        const float* ab = g_a + ((size_t)b * 64 + tid) * 3;
        a0s[tid] = ab[0]; a1s[tid] = ab[1]; a2s[tid] = ab[2];
    }
    if (tid < 51) lw[tid] = lin_w[tid];
    if (tid < 17) lb[tid] = lin_b[tid];
    __syncthreads();
    if (tid >= 64) return;

    const int t = tid;
    float s  = 1.f / (1.f + expf(-alpha[0]));
    float os = 1.f - s;

    float h00 = 0.f, h01 = 0.f, h11 = 0.f;
    for (int k = 0; k <= t; k++) {
        float mean = 0.5f * (h00 + h11);
        float diff = 0.5f * (h00 - h11);
        float rad  = sqrtf(diff * diff + h01 * h01);
        float r00, r01, r11;
        if (rad > 1e-20f) {
            float l1 = mean + rad, l2 = mean - rad;
            float m1 = fmaxf(l1, EPSV), m2 = fmaxf(l2, EPSV);
            float c1 = (m1 - m2) / (l1 - l2);
            float c0 = m1 - c1 * l1;
            r00 = c1 * h00 + c0;
            r01 = c1 * h01;
            r11 = c1 * h11 + c0;
        } else {
            if (mean >= EPSV) { r00 = h00; r01 = h01; r11 = h11; }
            else              { r00 = EPSV; r01 = 0.f; r11 = EPSV; }
        }
        h00 = fmaf(s, a0s[k], os * r00);
        h01 = fmaf(s, a1s[k], os * r01);
        h11 = fmaf(s, a2s[k], os * r11);
    }

    float mean = 0.5f * (h00 + h11);
    float diff = 0.5f * (h00 - h11);
    float rad  = sqrtf(diff * diff + h01 * h01);
    float l1 = mean + rad, l2 = mean - rad;
    float d  = l1 - l2;
    float c1 = (d > 0.f) ? (log1pf(d / l2) / d) : (1.f / l1);
    float c0 = logf(l2) - c1 * l2;
    float v0 = c1 * h00 + c0;
    float v1 = c1 * h01;
    float v2 = c1 * h11 + c0;

    float* o = out + ((size_t)b * 64 + t) * 17;
    #pragma unroll
    for (int j = 0; j < 17; j++)
        o[j] = fmaf(lw[j * 3], v0, fmaf(lw[j * 3 + 1], v1, fmaf(lw[j * 3 + 2], v2, lb[j])));
}

// ---------------------------------------------------------------------------
extern "C" void kernel_launch(void* const* d_in, const int* in_sizes, int n_in,
                              void* d_out, int out_size) {
    const float* x     = (const float*)d_in[0];  // (128,64,57,57)
    const float* W1    = (const float*)d_in[1];  // (57,20)
    const float* W2    = (const float*)d_in[2];  // (20,10)
    const float* W3    = (const float*)d_in[3];  // (10,2)
    const float* lin_w = (const float*)d_in[4];  // (17,3)
    const float* lin_b = (const float*)d_in[5];  // (17,)
    const float* alpha = (const float*)d_in[6];  // (1,)
    float* out = (float*)d_out;                  // (128,64,17)

    fused_kernel<<<BLOCKS, 256>>>(x, W1, W2, W3, lin_w, lin_b, alpha, out);
}

// round 17
// speedup vs baseline: 1.1574x; 1.1574x over previous
#include <cuda_runtime.h>
#include <cstdint>
#include <math.h>

#define EPSV 1e-4f
#define NM   3249            // 57*57 floats per matrix
#define WPB  4               // warps (=matrices) per block
#define BLOCKS 2048          // 8192 matrices / 4
#define BLK_PER_B 16         // 64 matrices per batch / 4 per block

// Scratch (allocation-free). Counter reset by last arriver -> graph-replay safe.
__device__ float g_a[128 * 64 * 3];
__device__ int   g_cnt[128];

__global__ void __launch_bounds__(128, 16)
fused_kernel(const float* __restrict__ x,
             const float* __restrict__ W1,
             const float* __restrict__ W2,
             const float* __restrict__ W3,
             const float* __restrict__ lin_w,
             const float* __restrict__ lin_b,
             const float* __restrict__ alpha,
             float* __restrict__ out) {
    __shared__ float2 sm_pq[57];
    __shared__ float  sm_w23[40];
    __shared__ float  sm_scan[260];     // a0|a1|a2 (64 each) + lw(51) + lb(17)
    __shared__ int    sm_last;

    const int tid  = threadIdx.x;
    const int wid  = tid >> 5;
    const int lane = tid & 31;
    const int blk  = blockIdx.x;

    // --- P = W1@W2@W3 into sm_pq ---
    if (tid < 40) {
        int j = tid >> 1, u = tid & 1;
        float s = 0.f;
        #pragma unroll
        for (int k = 0; k < 10; k++) s = fmaf(__ldg(W2 + j * 10 + k), __ldg(W3 + k * 2 + u), s);
        sm_w23[tid] = s;
    }
    __syncthreads();
    if (tid < 114) {
        int i = tid >> 1, u = tid & 1;
        float s = 0.f;
        #pragma unroll
        for (int j = 0; j < 20; j++) s = fmaf(__ldg(W1 + i * 20 + j), sm_w23[j * 2 + u], s);
        ((float*)&sm_pq[i])[u] = s;
    }
    __syncthreads();

    // --- Per-warp matrix: c = P^T X P with register-resident column weights ---
    const int gm = blk * WPB + wid;              // matrix id 0..8191
    const float* xm = x + (size_t)gm * NM;

    const float2 pk0 = sm_pq[lane];              // weight for k = lane
    const bool   hi  = (lane < 25);
    const float2 pk1 = hi ? sm_pq[32 + lane] : make_float2(0.f, 0.f);
    const int    off1 = hi ? (32 + lane) : 0;    // safe address (value masked by pk1=0)

    float c00 = 0.f, c01 = 0.f, c11 = 0.f;

    #define ROW(i_)                                                   \
    {                                                                 \
        const float* r = xm + 57 * (i_);                              \
        float a0 = r[lane];                                           \
        float a1 = r[off1];                                           \
        float2 pi = sm_pq[(i_)];                                      \
        float u = fmaf(a1, pk1.x, a0 * pk0.x);                        \
        float v = fmaf(a1, pk1.y, a0 * pk0.y);                        \
        c00 = fmaf(pi.x, u, c00);                                     \
        c01 = fmaf(pi.x, v, c01);                                     \
        c11 = fmaf(pi.y, v, c11);                                     \
    }

    #pragma unroll 4
    for (int i = 0; i < 56; i += 2) {            // 2-row software pipeline (MLP=4)
        ROW(i);
        ROW(i + 1);
    }
    ROW(56);
    #undef ROW

    // warp reduction (X symmetric -> c01 total well-defined)
    #pragma unroll
    for (int o = 16; o; o >>= 1) {
        c00 += __shfl_xor_sync(0xFFFFFFFFu, c00, o);
        c01 += __shfl_xor_sync(0xFFFFFFFFu, c01, o);
        c11 += __shfl_xor_sync(0xFFFFFFFFu, c11, o);
    }
    if (lane == 0) {
        float* o = g_a + (size_t)gm * 3;
        o[0] = c00; o[1] = c01; o[2] = c11;
    }
    __threadfence();
    __syncthreads();

    const int b = blk >> 4;                      // 16 blocks per batch
    if (tid == 0) {
        int old = atomicAdd(&g_cnt[b], 1);
        sm_last = (old == BLK_PER_B - 1);
        if (old == BLK_PER_B - 1) g_cnt[b] = 0;  // reset for graph replay
    }
    __syncthreads();
    if (!sm_last) return;

    // --- Scan phase (only last-arriving block per b) ---
    __threadfence();                             // acquire
    float* a0 = sm_scan;
    float* a1 = sm_scan + 64;
    float* a2 = sm_scan + 128;
    float* lw = sm_scan + 192;                   // 51
    float* lb = sm_scan + 243;                   // 17
    if (tid < 64) {
        const float* ab = g_a + ((size_t)b * 64 + tid) * 3;
        a0[tid] = ab[0]; a1[tid] = ab[1]; a2[tid] = ab[2];
    }
    if (tid < 51) lw[tid] = lin_w[tid];
    if (tid < 17) lb[tid] = lin_b[tid];
    __syncthreads();
    if (tid >= 64) return;

    const int t = tid;
    float s  = 1.f / (1.f + expf(-alpha[0]));
    float os = 1.f - s;

    float h00 = 0.f, h01 = 0.f, h11 = 0.f;
    for (int k = 0; k <= t; k++) {
        float mean = 0.5f * (h00 + h11);
        float diff = 0.5f * (h00 - h11);
        float rad  = sqrtf(diff * diff + h01 * h01);
        float r00, r01, r11;
        if (rad > 1e-20f) {
            float l1 = mean + rad, l2 = mean - rad;
            float m1 = fmaxf(l1, EPSV), m2 = fmaxf(l2, EPSV);
            float c1 = (m1 - m2) / (l1 - l2);
            float c0 = m1 - c1 * l1;
            r00 = c1 * h00 + c0;
            r01 = c1 * h01;
            r11 = c1 * h11 + c0;
        } else {
            if (mean >= EPSV) { r00 = h00; r01 = h01; r11 = h11; }
            else              { r00 = EPSV; r01 = 0.f; r11 = EPSV; }
        }
        h00 = fmaf(s, a0[k], os * r00);
        h01 = fmaf(s, a1[k], os * r01);
        h11 = fmaf(s, a2[k], os * r11);
    }

    float mean = 0.5f * (h00 + h11);
    float diff = 0.5f * (h00 - h11);
    float rad  = sqrtf(diff * diff + h01 * h01);
    float l1 = mean + rad, l2 = mean - rad;
    float d  = l1 - l2;
    float c1 = (d > 0.f) ? (log1pf(d / l2) / d) : (1.f / l1);
    float c0 = logf(l2) - c1 * l2;
    float v0 = c1 * h00 + c0;
    float v1 = c1 * h01;
    float v2 = c1 * h11 + c0;

    float* o = out + ((size_t)b * 64 + t) * 17;
    #pragma unroll
    for (int j = 0; j < 17; j++)
        o[j] = fmaf(lw[j * 3], v0, fmaf(lw[j * 3 + 1], v1, fmaf(lw[j * 3 + 2], v2, lb[j])));
}

// ---------------------------------------------------------------------------
extern "C" void kernel_launch(void* const* d_in, const int* in_sizes, int n_in,
                              void* d_out, int out_size) {
    const float* x     = (const float*)d_in[0];  // (128,64,57,57)
    const float* W1    = (const float*)d_in[1];  // (57,20)
    const float* W2    = (const float*)d_in[2];  // (20,10)
    const float* W3    = (const float*)d_in[3];  // (10,2)
    const float* lin_w = (const float*)d_in[4];  // (17,3)
    const float* lin_b = (const float*)d_in[5];  // (17,)
    const float* alpha = (const float*)d_in[6];  // (1,)
    float* out = (float*)d_out;                  // (128,64,17)

    fused_kernel<<<BLOCKS, 128>>>(x, W1, W2, W3, lin_w, lin_b, alpha, out);
}